// round 14
// baseline (speedup 1.0000x reference)
#include <cuda_runtime.h>
#include <cstdint>

#define NB 64
#define ND 4096
#define NV 50257

// ---------------- scratch (device globals; no allocs allowed) ----------------
__device__ float g_logits[(size_t)NB * NV];
__device__ float g_exp[(size_t)NB * NV];
__device__ float g_thresh[NB];

// ---------------- packed fp32x2 FMA (Blackwell FFMA2) ----------------
__device__ __forceinline__ unsigned long long ffma2(unsigned long long a,
                                                    unsigned long long b,
                                                    unsigned long long c) {
    unsigned long long d;
    asm("fma.rn.f32x2 %0, %1, %2, %3;" : "=l"(d) : "l"(a), "l"(b), "l"(c));
    return d;
}

// ---------------- GEMM: logits[b][v] = dot(h[b], W[v]) / T[b] ----------------
#define BKK 32
__global__ void __launch_bounds__(128)
gemm_kernel(const float* __restrict__ H,
            const float* __restrict__ W,
            const float* __restrict__ T) {
    __shared__ float As[BKK][64 + 4];
    __shared__ float Bs[BKK][256 + 4];
    const int tid = threadIdx.x;
    const int n0  = blockIdx.x * 128;
    const int tmg = tid >> 4;   // 0..7  (m group of 8 rows)
    const int tng = tid & 15;   // 0..15 (n group of 8 cols)

    unsigned long long acc[4][8];
#pragma unroll
    for (int i = 0; i < 4; i++)
#pragma unroll
        for (int j = 0; j < 8; j++) acc[i][j] = 0ull;

    for (int k0 = 0; k0 < ND; k0 += BKK) {
#pragma unroll
        for (int t = 0; t < 4; t++) {
            int fid = tid + t * 128;
            int m = fid >> 3, kq = fid & 7;
            float4 v = *(const float4*)(H + (size_t)m * ND + k0 + kq * 4);
            As[kq * 4 + 0][m] = v.x;
            As[kq * 4 + 1][m] = v.y;
            As[kq * 4 + 2][m] = v.z;
            As[kq * 4 + 3][m] = v.w;
        }
#pragma unroll
        for (int t = 0; t < 8; t++) {
            int fid = tid + t * 128;
            int n = fid >> 3, kq = fid & 7;
            int vr = n0 + n;
            float4 v = make_float4(0.f, 0.f, 0.f, 0.f);
            if (vr < NV) v = *(const float4*)(W + (size_t)vr * ND + k0 + kq * 4);
            *(float2*)&Bs[kq * 4 + 0][2 * n] = make_float2(v.x, v.x);
            *(float2*)&Bs[kq * 4 + 1][2 * n] = make_float2(v.y, v.y);
            *(float2*)&Bs[kq * 4 + 2][2 * n] = make_float2(v.z, v.z);
            *(float2*)&Bs[kq * 4 + 3][2 * n] = make_float2(v.w, v.w);
        }
        __syncthreads();
#pragma unroll 8
        for (int k = 0; k < BKK; k++) {
            float4 a0 = *(const float4*)&As[k][tmg * 8];
            float4 a1 = *(const float4*)&As[k][tmg * 8 + 4];
            float4 b0 = *(const float4*)&Bs[k][tng * 16];
            float4 b1 = *(const float4*)&Bs[k][tng * 16 + 4];
            float4 b2 = *(const float4*)&Bs[k][tng * 16 + 8];
            float4 b3 = *(const float4*)&Bs[k][tng * 16 + 12];
            unsigned long long ap[4], bp[8];
            ap[0] = ((const unsigned long long*)&a0)[0];
            ap[1] = ((const unsigned long long*)&a0)[1];
            ap[2] = ((const unsigned long long*)&a1)[0];
            ap[3] = ((const unsigned long long*)&a1)[1];
            bp[0] = ((const unsigned long long*)&b0)[0];
            bp[1] = ((const unsigned long long*)&b0)[1];
            bp[2] = ((const unsigned long long*)&b1)[0];
            bp[3] = ((const unsigned long long*)&b1)[1];
            bp[4] = ((const unsigned long long*)&b2)[0];
            bp[5] = ((const unsigned long long*)&b2)[1];
            bp[6] = ((const unsigned long long*)&b3)[0];
            bp[7] = ((const unsigned long long*)&b3)[1];
#pragma unroll
            for (int i = 0; i < 4; i++)
#pragma unroll
                for (int j = 0; j < 8; j++)
                    acc[i][j] = ffma2(ap[i], bp[j], acc[i][j]);
        }
        __syncthreads();
    }
    float tv[8];
#pragma unroll
    for (int i = 0; i < 8; i++) tv[i] = T[tmg * 8 + i];
#pragma unroll
    for (int i = 0; i < 4; i++) {
#pragma unroll
        for (int j = 0; j < 8; j++) {
            int n = n0 + tng * 8 + j;
            if (n < NV) {
                float2 v = *(float2*)&acc[i][j];
                int m0 = tmg * 8 + 2 * i;
                g_logits[(size_t)m0 * NV + n]       = __fdiv_rn(v.x, tv[2 * i]);
                g_logits[(size_t)(m0 + 1) * NV + n] = __fdiv_rn(v.y, tv[2 * i + 1]);
            }
        }
    }
}

// ---------------- stats + top-p threshold (one block per row) ----------------
// kept(v) <=> sum of probs strictly above p_v <= top_p. Bisect exp-threshold.
#define STH 256
__global__ void __launch_bounds__(STH)
stats_kernel(const float* __restrict__ top_p) {
    const int b = blockIdx.x, tid = threadIdx.x;
    const float* L = g_logits + (size_t)b * NV;
    float* E = g_exp + (size_t)b * NV;
    __shared__ float red[STH];

    float m = -3.4e38f;
    for (int v = tid; v < NV; v += STH) m = fmaxf(m, L[v]);
    red[tid] = m; __syncthreads();
    for (int s = STH / 2; s > 0; s >>= 1) {
        if (tid < s) red[tid] = fmaxf(red[tid], red[tid + s]);
        __syncthreads();
    }
    const float M = red[0]; __syncthreads();

    float sum = 0.f;
    for (int v = tid; v < NV; v += STH) {
        float e = expf(L[v] - M);
        E[v] = e;
        sum += e;
    }
    red[tid] = sum; __syncthreads();
    for (int s = STH / 2; s > 0; s >>= 1) {
        if (tid < s) red[tid] += red[tid + s];
        __syncthreads();
    }
    const float Z = red[0]; __syncthreads();
    const float PZ = top_p[b] * Z;

    float lo = 0.f, hi = 1.0f;
    for (int it = 0; it < 45; it++) {
        float mid = 0.5f * (lo + hi);
        float s = 0.f;
        for (int v = tid; v < NV; v += STH) {
            float e = E[v];
            if (e > mid) s += e;
        }
        red[tid] = s; __syncthreads();
        for (int st = STH / 2; st > 0; st >>= 1) {
            if (tid < st) red[tid] += red[tid + st];
            __syncthreads();
        }
        float S = red[0]; __syncthreads();
        if (S > PZ) lo = mid; else hi = mid;
    }
    if (tid == 0) g_thresh[b] = lo;
}

// ---------------- JAX threefry2x32 (key = (0,42)) ----------------
__device__ __forceinline__ uint2 threefry(unsigned x0, unsigned x1) {
    const unsigned ks0 = 0u, ks1 = 42u;
    const unsigned ks2 = 0u ^ 42u ^ 0x1BD11BDAu;
    x0 += ks0; x1 += ks1;
#define TF_ROUND(r) { x0 += x1; x1 = (x1 << (r)) | (x1 >> (32 - (r))); x1 ^= x0; }
    TF_ROUND(13) TF_ROUND(15) TF_ROUND(26) TF_ROUND(6)
    x0 += ks1; x1 += ks2 + 1u;
    TF_ROUND(17) TF_ROUND(29) TF_ROUND(16) TF_ROUND(24)
    x0 += ks2; x1 += ks0 + 2u;
    TF_ROUND(13) TF_ROUND(15) TF_ROUND(26) TF_ROUND(6)
    x0 += ks0; x1 += ks1 + 3u;
    TF_ROUND(17) TF_ROUND(29) TF_ROUND(16) TF_ROUND(24)
    x0 += ks1; x1 += ks2 + 4u;
    TF_ROUND(13) TF_ROUND(15) TF_ROUND(26) TF_ROUND(6)
    x0 += ks2; x1 += ks0 + 5u;
#undef TF_ROUND
    return make_uint2(x0, x1);
}

// ---------------- categorical sample: argmax(logit + gumbel) over kept ----------------
// PARTITIONABLE threefry (JAX >= 0.4.30 default): counter mode, per element i
// the counter is (hi,lo) = (i>>32, i&0xffffffff) = (0, i) here, and the 32-bit
// random value is the XOR of the two threefry output words.
__global__ void __launch_bounds__(STH)
sample_kernel(float* __restrict__ out) {
    const int b = blockIdx.x, tid = threadIdx.x;
    const float* L = g_logits + (size_t)b * NV;
    const float* E = g_exp + (size_t)b * NV;
    const float thr = g_thresh[b];
    __shared__ float rv[STH];
    __shared__ int   ri[STH];

    float best = -3.4e38f;
    int   bi = 0x7fffffff;
    for (int v = tid; v < NV; v += STH) {
        if (E[v] > thr) {
            float l = L[v];
            // max gumbel = -log(-log(1-2^-23)) ~= 15.94 < 17
            if (l + 17.0f >= best) {
                unsigned i = (unsigned)(b * NV + v);
                uint2 r = threefry(0u, i);
                unsigned bits = r.x ^ r.y;
                float u = __uint_as_float((bits >> 9) | 0x3f800000u) - 1.0f;
                if (u == 0.f) u = 1.17549435e-38f;   // jax uniform minval = tiny
                float nl  = -logf(u);
                float gum = -logf(nl);
                float val = l + gum;
                if (val > best) { best = val; bi = v; }
            }
        }
    }
    rv[tid] = best; ri[tid] = bi; __syncthreads();
    for (int s = STH / 2; s > 0; s >>= 1) {
        if (tid < s) {
            if (rv[tid + s] > rv[tid] ||
                (rv[tid + s] == rv[tid] && ri[tid + s] < ri[tid])) {
                rv[tid] = rv[tid + s];
                ri[tid] = ri[tid + s];
            }
        }
        __syncthreads();
    }
    if (tid == 0) out[b] = (float)ri[0];
}

// ---------------- launch ----------------
// Inputs may arrive in metadata (alphabetical) or signature order; the two
// matrices have unique element counts, so assign by size. The two 64-element
// vectors keep relative order (temperature before top_p) under both schemes.
extern "C" void kernel_launch(void* const* d_in, const int* in_sizes, int n_in,
                              void* d_out, int out_size) {
    const float* H  = nullptr;
    const float* W  = nullptr;
    const float* T  = nullptr;
    const float* TP = nullptr;
    for (int i = 0; i < n_in; i++) {
        if (in_sizes[i] == NB * ND) {
            H = (const float*)d_in[i];
        } else if (in_sizes[i] == NV * ND) {
            W = (const float*)d_in[i];
        } else if (in_sizes[i] == NB) {
            if (!T) T = (const float*)d_in[i];
            else    TP = (const float*)d_in[i];
        }
    }
    if (!H || !W || !T || !TP) {   // fallback: signature order
        H  = (const float*)d_in[0];
        W  = (const float*)d_in[1];
        T  = (const float*)d_in[2];
        TP = (const float*)d_in[3];
    }
    float* out = (float*)d_out;

    gemm_kernel<<<(NV + 127) / 128, 128>>>(H, W, T);
    stats_kernel<<<NB, STH>>>(TP);
    sample_kernel<<<NB, STH>>>(out);
}

// round 15
// speedup vs baseline: 1.1074x; 1.1074x over previous
#include <cuda_runtime.h>
#include <cstdint>

#define NB 64
#define ND 4096
#define NV 50257

// ---------------- scratch (device globals; no allocs allowed) ----------------
__device__ float g_part0[(size_t)NB * NV];
__device__ float g_part1[(size_t)NB * NV];
__device__ float g_part2[(size_t)NB * NV];
__device__ float g_logits[(size_t)NB * NV];
__device__ float g_exp[(size_t)NB * NV];
__device__ float g_thresh[NB];

// ---------------- packed fp32x2 FMA (Blackwell FFMA2) ----------------
__device__ __forceinline__ unsigned long long ffma2(unsigned long long a,
                                                    unsigned long long b,
                                                    unsigned long long c) {
    unsigned long long d;
    asm("fma.rn.f32x2 %0, %1, %2, %3;" : "=l"(d) : "l"(a), "l"(b), "l"(c));
    return d;
}

// ---------------- GEMM partials: part_s[b][v] = dot(h[b], W[v]) over k-split s ----
// Split-K3 over 128 k-tiles of 32: {43,43,42}. Grid (393, 3), 128 thr.
// Each block: M=64 x N=128 tile, 8x8 per thread via fp32x2.
#define BKK 32
__global__ void __launch_bounds__(128)
gemm_kernel(const float* __restrict__ H,
            const float* __restrict__ W) {
    __shared__ float As[BKK][64 + 4];
    __shared__ float Bs[BKK][256 + 4];
    const int tid = threadIdx.x;
    const int n0  = blockIdx.x * 128;
    const int s   = blockIdx.y;
    const int tmg = tid >> 4;   // 0..7  (m group of 8 rows)
    const int tng = tid & 15;   // 0..15 (n group of 8 cols)

    const int tile0  = (s == 0) ? 0 : (s == 1 ? 43 : 86);
    const int ntiles = (s == 2) ? 42 : 43;
    const int kbeg = tile0 * BKK;
    const int kend = kbeg + ntiles * BKK;

    float* out = (s == 0) ? g_part0 : (s == 1 ? g_part1 : g_part2);

    unsigned long long acc[4][8];
#pragma unroll
    for (int i = 0; i < 4; i++)
#pragma unroll
        for (int j = 0; j < 8; j++) acc[i][j] = 0ull;

    for (int k0 = kbeg; k0 < kend; k0 += BKK) {
#pragma unroll
        for (int t = 0; t < 4; t++) {
            int fid = tid + t * 128;
            int m = fid >> 3, kq = fid & 7;
            float4 v = *(const float4*)(H + (size_t)m * ND + k0 + kq * 4);
            As[kq * 4 + 0][m] = v.x;
            As[kq * 4 + 1][m] = v.y;
            As[kq * 4 + 2][m] = v.z;
            As[kq * 4 + 3][m] = v.w;
        }
#pragma unroll
        for (int t = 0; t < 8; t++) {
            int fid = tid + t * 128;
            int n = fid >> 3, kq = fid & 7;
            int vr = n0 + n;
            float4 v = make_float4(0.f, 0.f, 0.f, 0.f);
            if (vr < NV) v = *(const float4*)(W + (size_t)vr * ND + k0 + kq * 4);
            *(float2*)&Bs[kq * 4 + 0][2 * n] = make_float2(v.x, v.x);
            *(float2*)&Bs[kq * 4 + 1][2 * n] = make_float2(v.y, v.y);
            *(float2*)&Bs[kq * 4 + 2][2 * n] = make_float2(v.z, v.z);
            *(float2*)&Bs[kq * 4 + 3][2 * n] = make_float2(v.w, v.w);
        }
        __syncthreads();
#pragma unroll 8
        for (int k = 0; k < BKK; k++) {
            float4 a0 = *(const float4*)&As[k][tmg * 8];
            float4 a1 = *(const float4*)&As[k][tmg * 8 + 4];
            float4 b0 = *(const float4*)&Bs[k][tng * 16];
            float4 b1 = *(const float4*)&Bs[k][tng * 16 + 4];
            float4 b2 = *(const float4*)&Bs[k][tng * 16 + 8];
            float4 b3 = *(const float4*)&Bs[k][tng * 16 + 12];
            unsigned long long ap[4], bp[8];
            ap[0] = ((const unsigned long long*)&a0)[0];
            ap[1] = ((const unsigned long long*)&a0)[1];
            ap[2] = ((const unsigned long long*)&a1)[0];
            ap[3] = ((const unsigned long long*)&a1)[1];
            bp[0] = ((const unsigned long long*)&b0)[0];
            bp[1] = ((const unsigned long long*)&b0)[1];
            bp[2] = ((const unsigned long long*)&b1)[0];
            bp[3] = ((const unsigned long long*)&b1)[1];
            bp[4] = ((const unsigned long long*)&b2)[0];
            bp[5] = ((const unsigned long long*)&b2)[1];
            bp[6] = ((const unsigned long long*)&b3)[0];
            bp[7] = ((const unsigned long long*)&b3)[1];
#pragma unroll
            for (int i = 0; i < 4; i++)
#pragma unroll
                for (int j = 0; j < 8; j++)
                    acc[i][j] = ffma2(ap[i], bp[j], acc[i][j]);
        }
        __syncthreads();
    }
#pragma unroll
    for (int i = 0; i < 4; i++) {
#pragma unroll
        for (int j = 0; j < 8; j++) {
            int n = n0 + tng * 8 + j;
            if (n < NV) {
                float2 v = *(float2*)&acc[i][j];
                int m0 = tmg * 8 + 2 * i;
                out[(size_t)m0 * NV + n]       = v.x;
                out[(size_t)(m0 + 1) * NV + n] = v.y;
            }
        }
    }
}

// ---------------- block reductions (1024 thr, deterministic) ----------------
__device__ __forceinline__ float warpRedMax(float v) {
#pragma unroll
    for (int o = 16; o > 0; o >>= 1) v = fmaxf(v, __shfl_xor_sync(0xffffffffu, v, o));
    return v;
}
__device__ __forceinline__ float warpRedSum(float v) {
#pragma unroll
    for (int o = 16; o > 0; o >>= 1) v += __shfl_xor_sync(0xffffffffu, v, o);
    return v;
}
__device__ __forceinline__ float blockRedMax(float v, float* sred, float* bcast) {
    int tid = threadIdx.x, wid = tid >> 5, lid = tid & 31;
    __syncthreads();
    v = warpRedMax(v);
    if (lid == 0) sred[wid] = v;
    __syncthreads();
    if (wid == 0) {
        float x = sred[lid];
        x = warpRedMax(x);
        if (lid == 0) *bcast = x;
    }
    __syncthreads();
    return *bcast;
}
__device__ __forceinline__ float blockRedSum(float v, float* sred, float* bcast) {
    int tid = threadIdx.x, wid = tid >> 5, lid = tid & 31;
    __syncthreads();
    v = warpRedSum(v);
    if (lid == 0) sred[wid] = v;
    __syncthreads();
    if (wid == 0) {
        float x = sred[lid];
        x = warpRedSum(x);
        if (lid == 0) *bcast = x;
    }
    __syncthreads();
    return *bcast;
}

// ---------------- stats: combine partials, /T, softmax stats, top-p threshold ----
// Octary bisection: 7 thresholds per sweep, 16 sweeps => interval / 8^16 = 2^-48.
// Invariant: S(lo) > PZ >= S(hi), kept(v) <=> e_v > lo. Fully deterministic.
__global__ void __launch_bounds__(1024)
stats_kernel(const float* __restrict__ T, const float* __restrict__ top_p) {
    const int b = blockIdx.x, tid = threadIdx.x;
    const float* P0 = g_part0 + (size_t)b * NV;
    const float* P1 = g_part1 + (size_t)b * NV;
    const float* P2 = g_part2 + (size_t)b * NV;
    float* L = g_logits + (size_t)b * NV;
    float* E = g_exp + (size_t)b * NV;
    __shared__ float sred[32];
    __shared__ float bcast;

    // pass A: combine partials, divide by temperature, row max
    const float tb = T[b];
    float m = -3.4e38f;
    for (int v = tid; v < NV; v += 1024) {
        float l = (P0[v] + P1[v]) + P2[v];
        l = __fdiv_rn(l, tb);
        L[v] = l;
        m = fmaxf(m, l);
    }
    const float M = blockRedMax(m, sred, &bcast);

    // pass B: exp + Z
    float z = 0.f;
    for (int v = tid; v < NV; v += 1024) {
        float e = expf(L[v] - M);
        E[v] = e;
        z += e;
    }
    const float Z = blockRedSum(z, sred, &bcast);
    const float PZ = top_p[b] * Z;

    // octary bisection on exp-threshold in [0,1]
    float lo = 0.f, hi = 1.0f;
    for (int it = 0; it < 16; it++) {
        float w = hi - lo;
        float t[7];
#pragma unroll
        for (int j = 0; j < 7; j++) t[j] = lo + w * ((float)(j + 1) * 0.125f);
        float ss[7] = {0.f, 0.f, 0.f, 0.f, 0.f, 0.f, 0.f};
        for (int v = tid; v < NV; v += 1024) {
            float e = E[v];
#pragma unroll
            for (int j = 0; j < 7; j++)
                if (e > t[j]) ss[j] += e;
        }
        float S[7];
#pragma unroll
        for (int j = 0; j < 7; j++) S[j] = blockRedSum(ss[j], sred, &bcast);
        // largest j with S_j > PZ (S nonincreasing in j)
        int jstar = -1;
#pragma unroll
        for (int j = 0; j < 7; j++)
            if (S[j] > PZ) jstar = j;
        if (jstar < 0) {
            hi = t[0];
        } else {
            lo = t[jstar];
            if (jstar < 6) hi = t[jstar + 1];
        }
    }
    if (tid == 0) g_thresh[b] = lo;
}

// ---------------- JAX threefry2x32 (key = (0,42)) ----------------
__device__ __forceinline__ uint2 threefry(unsigned x0, unsigned x1) {
    const unsigned ks0 = 0u, ks1 = 42u;
    const unsigned ks2 = 0u ^ 42u ^ 0x1BD11BDAu;
    x0 += ks0; x1 += ks1;
#define TF_ROUND(r) { x0 += x1; x1 = (x1 << (r)) | (x1 >> (32 - (r))); x1 ^= x0; }
    TF_ROUND(13) TF_ROUND(15) TF_ROUND(26) TF_ROUND(6)
    x0 += ks1; x1 += ks2 + 1u;
    TF_ROUND(17) TF_ROUND(29) TF_ROUND(16) TF_ROUND(24)
    x0 += ks2; x1 += ks0 + 2u;
    TF_ROUND(13) TF_ROUND(15) TF_ROUND(26) TF_ROUND(6)
    x0 += ks0; x1 += ks1 + 3u;
    TF_ROUND(17) TF_ROUND(29) TF_ROUND(16) TF_ROUND(24)
    x0 += ks1; x1 += ks2 + 4u;
    TF_ROUND(13) TF_ROUND(15) TF_ROUND(26) TF_ROUND(6)
    x0 += ks2; x1 += ks0 + 5u;
#undef TF_ROUND
    return make_uint2(x0, x1);
}

// ---------------- categorical sample: argmax(logit + gumbel) over kept ----------------
// Partitionable threefry (JAX >= 0.4.30 default): counter (0, i), bits = out0 ^ out1.
#define STH 256
__global__ void __launch_bounds__(STH)
sample_kernel(float* __restrict__ out) {
    const int b = blockIdx.x, tid = threadIdx.x;
    const float* L = g_logits + (size_t)b * NV;
    const float* E = g_exp + (size_t)b * NV;
    const float thr = g_thresh[b];
    __shared__ float rv[STH];
    __shared__ int   ri[STH];

    float best = -3.4e38f;
    int   bi = 0x7fffffff;
    for (int v = tid; v < NV; v += STH) {
        if (E[v] > thr) {
            float l = L[v];
            // max gumbel ~= 16.64 < 17
            if (l + 17.0f >= best) {
                unsigned i = (unsigned)(b * NV + v);
                uint2 r = threefry(0u, i);
                unsigned bits = r.x ^ r.y;
                float u = __uint_as_float((bits >> 9) | 0x3f800000u) - 1.0f;
                if (u == 0.f) u = 1.17549435e-38f;   // jax uniform minval = tiny
                float nl  = -logf(u);
                float gum = -logf(nl);
                float val = l + gum;
                if (val > best) { best = val; bi = v; }
            }
        }
    }
    rv[tid] = best; ri[tid] = bi; __syncthreads();
    for (int s = STH / 2; s > 0; s >>= 1) {
        if (tid < s) {
            if (rv[tid + s] > rv[tid] ||
                (rv[tid + s] == rv[tid] && ri[tid + s] < ri[tid])) {
                rv[tid] = rv[tid + s];
                ri[tid] = ri[tid + s];
            }
        }
        __syncthreads();
    }
    if (tid == 0) out[b] = (float)ri[0];
}

// ---------------- launch ----------------
extern "C" void kernel_launch(void* const* d_in, const int* in_sizes, int n_in,
                              void* d_out, int out_size) {
    const float* H  = nullptr;
    const float* W  = nullptr;
    const float* T  = nullptr;
    const float* TP = nullptr;
    for (int i = 0; i < n_in; i++) {
        if (in_sizes[i] == NB * ND) {
            H = (const float*)d_in[i];
        } else if (in_sizes[i] == NV * ND) {
            W = (const float*)d_in[i];
        } else if (in_sizes[i] == NB) {
            if (!T) T = (const float*)d_in[i];
            else    TP = (const float*)d_in[i];
        }
    }
    if (!H || !W || !T || !TP) {   // fallback: signature order
        H  = (const float*)d_in[0];
        W  = (const float*)d_in[1];
        T  = (const float*)d_in[2];
        TP = (const float*)d_in[3];
    }
    float* out = (float*)d_out;

    dim3 gg((NV + 127) / 128, 3);
    gemm_kernel<<<gg, 128>>>(H, W);
    stats_kernel<<<NB, 1024>>>(T, TP);
    sample_kernel<<<NB, STH>>>(out);
}

// round 16
// speedup vs baseline: 2.5861x; 2.3353x over previous
#include <cuda_runtime.h>
#include <cstdint>

#define NB 64
#define ND 4096
#define NV 50257

// ---------------- scratch (device globals; no allocs allowed) ----------------
__device__ float g_At[(size_t)ND * NB];     // A transposed: At[k][m]
__device__ float g_part0[(size_t)NB * NV];
__device__ float g_part1[(size_t)NB * NV];
__device__ float g_part2[(size_t)NB * NV];
__device__ float g_logits[(size_t)NB * NV];
__device__ float g_exp[(size_t)NB * NV];
__device__ float g_thresh[NB];

// ---------------- packed fp32x2 FMA (Blackwell FFMA2) ----------------
__device__ __forceinline__ unsigned long long ffma2(unsigned long long a,
                                                    unsigned long long b,
                                                    unsigned long long c) {
    unsigned long long d;
    asm("fma.rn.f32x2 %0, %1, %2, %3;" : "=l"(d) : "l"(a), "l"(b), "l"(c));
    return d;
}

// ---------------- cp.async helpers ----------------
__device__ __forceinline__ void cp16(float* dst, const float* src) {
    unsigned d = (unsigned)__cvta_generic_to_shared(dst);
    asm volatile("cp.async.cg.shared.global [%0], [%1], 16;" :: "r"(d), "l"(src));
}
__device__ __forceinline__ void cp16_pred(float* dst, const float* src, bool ok) {
    unsigned d = (unsigned)__cvta_generic_to_shared(dst);
    int sz = ok ? 16 : 0;   // src-size 0 => zero-fill, no global read
    asm volatile("cp.async.cg.shared.global [%0], [%1], 16, %2;"
                 :: "r"(d), "l"(src), "r"(sz));
}
#define CP_COMMIT() asm volatile("cp.async.commit_group;")
#define CP_WAIT0()  asm volatile("cp.async.wait_group 0;")

// ---------------- A pre-transpose: At[k][m] = H[m][k] (1 MB, once) ----------------
__global__ void __launch_bounds__(256)
transpose_kernel(const float* __restrict__ H) {
    int g = blockIdx.x * 256 + threadIdx.x;   // 0 .. 64*4096-1
    int m = g >> 12, k = g & 4095;
    g_At[(size_t)k * NB + m] = H[g];
}

// ---------------- GEMM partials, split-K3, cp.async double-buffered ----------------
// Block: M=64 x N=128, BKK=32, 128 threads, 8m x 8n per thread.
// acc[i][j]: m-pair (tmg*8+2i, +1) x n = tng + 16j. A pairs come packed from
// smem (k-major); B scalar loads (n-major, pad 36 -> worst 2-way conflict),
// duplicated to (w,w) via mov.b64.
#define BKK  32
#define BPAD 36
#define GEMM_SMEM ((2*BKK*64 + 2*128*BPAD) * 4)   // 53248 B

__global__ void __launch_bounds__(128, 3)
gemm_kernel(const float* __restrict__ W) {
    extern __shared__ float sm[];
    float* Asm = sm;                   // [2][BKK][64]
    float* Bsm = sm + 2 * BKK * 64;    // [2][128][BPAD]

    const int tid = threadIdx.x;
    const int n0  = blockIdx.x * 128;
    const int s   = blockIdx.y;
    const int tmg = tid >> 4;    // 0..7
    const int tng = tid & 15;    // 0..15

    const int tile0  = (s == 0) ? 0 : (s == 1 ? 43 : 86);
    const int ntiles = (s == 2) ? 42 : 43;
    const int kbeg   = tile0 * BKK;

    // B row for this thread's cp.async duty
    const int  gn   = n0 + tid;
    const bool bok  = gn < NV;
    const float* bsrc_base = W + (size_t)(bok ? gn : 0) * ND;

    unsigned long long acc[4][8];
#pragma unroll
    for (int i = 0; i < 4; i++)
#pragma unroll
        for (int j = 0; j < 8; j++) acc[i][j] = 0ull;

    // prefetch tile 0
    {
        const float* asrc = g_At + (size_t)kbeg * 64;
#pragma unroll
        for (int c = 0; c < 4; c++) {
            int chunk = tid + c * 128;
            cp16(Asm + chunk * 4, asrc + chunk * 4);
        }
        float* brow = Bsm + tid * BPAD;
        const float* bsrc = bsrc_base + kbeg;
#pragma unroll
        for (int c = 0; c < 8; c++) cp16_pred(brow + c * 4, bsrc + c * 4, bok);
        CP_COMMIT();
    }

    int buf = 0;
    for (int t = 0; t < ntiles; t++) {
        CP_WAIT0();
        __syncthreads();

        if (t + 1 < ntiles) {
            int k0n = kbeg + (t + 1) * BKK;
            int nb  = buf ^ 1;
            const float* asrc = g_At + (size_t)k0n * 64;
#pragma unroll
            for (int c = 0; c < 4; c++) {
                int chunk = tid + c * 128;
                cp16(Asm + nb * BKK * 64 + chunk * 4, asrc + chunk * 4);
            }
            float* brow = Bsm + nb * 128 * BPAD + tid * BPAD;
            const float* bsrc = bsrc_base + k0n;
#pragma unroll
            for (int c = 0; c < 8; c++) cp16_pred(brow + c * 4, bsrc + c * 4, bok);
            CP_COMMIT();
        }

        const float* Ab = Asm + buf * BKK * 64;
        const float* Bb = Bsm + buf * 128 * BPAD;
#pragma unroll 4
        for (int k = 0; k < BKK; k++) {
            float4 a01 = *(const float4*)(Ab + k * 64 + tmg * 8);
            float4 a23 = *(const float4*)(Ab + k * 64 + tmg * 8 + 4);
            unsigned long long ap[4];
            ap[0] = ((const unsigned long long*)&a01)[0];
            ap[1] = ((const unsigned long long*)&a01)[1];
            ap[2] = ((const unsigned long long*)&a23)[0];
            ap[3] = ((const unsigned long long*)&a23)[1];
            unsigned long long bp[8];
#pragma unroll
            for (int j = 0; j < 8; j++) {
                float w = Bb[(tng + 16 * j) * BPAD + k];
                unsigned wu = __float_as_uint(w);
                asm("mov.b64 %0, {%1, %1};" : "=l"(bp[j]) : "r"(wu));
            }
#pragma unroll
            for (int i = 0; i < 4; i++)
#pragma unroll
                for (int j = 0; j < 8; j++)
                    acc[i][j] = ffma2(ap[i], bp[j], acc[i][j]);
        }
        buf ^= 1;
    }

    float* outp = (s == 0) ? g_part0 : (s == 1 ? g_part1 : g_part2);
#pragma unroll
    for (int i = 0; i < 4; i++) {
        int m0 = tmg * 8 + 2 * i;
#pragma unroll
        for (int j = 0; j < 8; j++) {
            int n = n0 + tng + 16 * j;
            if (n < NV) {
                float2 v = *(float2*)&acc[i][j];
                outp[(size_t)m0 * NV + n]       = v.x;
                outp[(size_t)(m0 + 1) * NV + n] = v.y;
            }
        }
    }
}

// ---------------- block reductions (deterministic) ----------------
__device__ __forceinline__ float warpRedMax(float v) {
#pragma unroll
    for (int o = 16; o > 0; o >>= 1) v = fmaxf(v, __shfl_xor_sync(0xffffffffu, v, o));
    return v;
}
__device__ __forceinline__ float warpRedSum(float v) {
#pragma unroll
    for (int o = 16; o > 0; o >>= 1) v += __shfl_xor_sync(0xffffffffu, v, o);
    return v;
}
__device__ __forceinline__ float blockRedMax(float v, float* sred, float* bcast) {
    int tid = threadIdx.x, wid = tid >> 5, lid = tid & 31;
    __syncthreads();
    v = warpRedMax(v);
    if (lid == 0) sred[wid] = v;
    __syncthreads();
    if (wid == 0) {
        float x = sred[lid];
        x = warpRedMax(x);
        if (lid == 0) *bcast = x;
    }
    __syncthreads();
    return *bcast;
}
__device__ __forceinline__ float blockRedSum(float v, float* sred, float* bcast) {
    int tid = threadIdx.x, wid = tid >> 5, lid = tid & 31;
    __syncthreads();
    v = warpRedSum(v);
    if (lid == 0) sred[wid] = v;
    __syncthreads();
    if (wid == 0) {
        float x = sred[lid];
        x = warpRedSum(x);
        if (lid == 0) *bcast = x;
    }
    __syncthreads();
    return *bcast;
}

// ---------------- stats: combine partials, /T, softmax, octary top-p bisect ----
__global__ void __launch_bounds__(1024)
stats_kernel(const float* __restrict__ T, const float* __restrict__ top_p) {
    const int b = blockIdx.x, tid = threadIdx.x;
    const float* P0 = g_part0 + (size_t)b * NV;
    const float* P1 = g_part1 + (size_t)b * NV;
    const float* P2 = g_part2 + (size_t)b * NV;
    float* L = g_logits + (size_t)b * NV;
    float* E = g_exp + (size_t)b * NV;
    __shared__ float sred[32];
    __shared__ float bcast;

    const float tb = T[b];
    float m = -3.4e38f;
    for (int v = tid; v < NV; v += 1024) {
        float l = (P0[v] + P1[v]) + P2[v];
        l = __fdiv_rn(l, tb);
        L[v] = l;
        m = fmaxf(m, l);
    }
    const float M = blockRedMax(m, sred, &bcast);

    float z = 0.f;
    for (int v = tid; v < NV; v += 1024) {
        float e = expf(L[v] - M);
        E[v] = e;
        z += e;
    }
    const float Z = blockRedSum(z, sred, &bcast);
    const float PZ = top_p[b] * Z;

    float lo = 0.f, hi = 1.0f;
    for (int it = 0; it < 16; it++) {
        float w = hi - lo;
        float t[7];
#pragma unroll
        for (int j = 0; j < 7; j++) t[j] = lo + w * ((float)(j + 1) * 0.125f);
        float ss[7] = {0.f, 0.f, 0.f, 0.f, 0.f, 0.f, 0.f};
        for (int v = tid; v < NV; v += 1024) {
            float e = E[v];
#pragma unroll
            for (int j = 0; j < 7; j++)
                if (e > t[j]) ss[j] += e;
        }
        float S[7];
#pragma unroll
        for (int j = 0; j < 7; j++) S[j] = blockRedSum(ss[j], sred, &bcast);
        int jstar = -1;
#pragma unroll
        for (int j = 0; j < 7; j++)
            if (S[j] > PZ) jstar = j;
        if (jstar < 0) {
            hi = t[0];
        } else {
            lo = t[jstar];
            if (jstar < 6) hi = t[jstar + 1];
        }
    }
    if (tid == 0) g_thresh[b] = lo;
}

// ---------------- JAX threefry2x32 (key = (0,42)) ----------------
__device__ __forceinline__ uint2 threefry(unsigned x0, unsigned x1) {
    const unsigned ks0 = 0u, ks1 = 42u;
    const unsigned ks2 = 0u ^ 42u ^ 0x1BD11BDAu;
    x0 += ks0; x1 += ks1;
#define TF_ROUND(r) { x0 += x1; x1 = (x1 << (r)) | (x1 >> (32 - (r))); x1 ^= x0; }
    TF_ROUND(13) TF_ROUND(15) TF_ROUND(26) TF_ROUND(6)
    x0 += ks1; x1 += ks2 + 1u;
    TF_ROUND(17) TF_ROUND(29) TF_ROUND(16) TF_ROUND(24)
    x0 += ks2; x1 += ks0 + 2u;
    TF_ROUND(13) TF_ROUND(15) TF_ROUND(26) TF_ROUND(6)
    x0 += ks0; x1 += ks1 + 3u;
    TF_ROUND(17) TF_ROUND(29) TF_ROUND(16) TF_ROUND(24)
    x0 += ks1; x1 += ks2 + 4u;
    TF_ROUND(13) TF_ROUND(15) TF_ROUND(26) TF_ROUND(6)
    x0 += ks2; x1 += ks0 + 5u;
#undef TF_ROUND
    return make_uint2(x0, x1);
}

// ---------------- categorical sample: argmax(logit + gumbel) over kept ----------------
// Partitionable threefry (JAX >= 0.4.30 default): counter (0, i), bits = out0 ^ out1.
#define STH 256
__global__ void __launch_bounds__(STH)
sample_kernel(float* __restrict__ out) {
    const int b = blockIdx.x, tid = threadIdx.x;
    const float* L = g_logits + (size_t)b * NV;
    const float* E = g_exp + (size_t)b * NV;
    const float thr = g_thresh[b];
    __shared__ float rv[STH];
    __shared__ int   ri[STH];

    float best = -3.4e38f;
    int   bi = 0x7fffffff;
    for (int v = tid; v < NV; v += STH) {
        if (E[v] > thr) {
            float l = L[v];
            if (l + 17.0f >= best) {   // max gumbel ~= 16.64
                unsigned i = (unsigned)(b * NV + v);
                uint2 r = threefry(0u, i);
                unsigned bits = r.x ^ r.y;
                float u = __uint_as_float((bits >> 9) | 0x3f800000u) - 1.0f;
                if (u == 0.f) u = 1.17549435e-38f;
                float nl  = -logf(u);
                float gum = -logf(nl);
                float val = l + gum;
                if (val > best) { best = val; bi = v; }
            }
        }
    }
    rv[tid] = best; ri[tid] = bi; __syncthreads();
    for (int s = STH / 2; s > 0; s >>= 1) {
        if (tid < s) {
            if (rv[tid + s] > rv[tid] ||
                (rv[tid + s] == rv[tid] && ri[tid + s] < ri[tid])) {
                rv[tid] = rv[tid + s];
                ri[tid] = ri[tid + s];
            }
        }
        __syncthreads();
    }
    if (tid == 0) out[b] = (float)ri[0];
}

// ---------------- launch ----------------
extern "C" void kernel_launch(void* const* d_in, const int* in_sizes, int n_in,
                              void* d_out, int out_size) {
    const float* H  = nullptr;
    const float* W  = nullptr;
    const float* T  = nullptr;
    const float* TP = nullptr;
    for (int i = 0; i < n_in; i++) {
        if (in_sizes[i] == NB * ND) {
            H = (const float*)d_in[i];
        } else if (in_sizes[i] == NV * ND) {
            W = (const float*)d_in[i];
        } else if (in_sizes[i] == NB) {
            if (!T) T = (const float*)d_in[i];
            else    TP = (const float*)d_in[i];
        }
    }
    if (!H || !W || !T || !TP) {   // fallback: signature order
        H  = (const float*)d_in[0];
        W  = (const float*)d_in[1];
        T  = (const float*)d_in[2];
        TP = (const float*)d_in[3];
    }
    float* out = (float*)d_out;

    cudaFuncSetAttribute(gemm_kernel,
                         cudaFuncAttributeMaxDynamicSharedMemorySize, GEMM_SMEM);

    transpose_kernel<<<(NB * ND) / 256, 256>>>(H);
    dim3 gg((NV + 127) / 128, 3);
    gemm_kernel<<<gg, 128, GEMM_SMEM>>>(W);
    stats_kernel<<<NB, 1024>>>(T, TP);
    sample_kernel<<<NB, STH>>>(out);
}

// round 17
// speedup vs baseline: 2.9852x; 1.1543x over previous
#include <cuda_runtime.h>
#include <cstdint>

#define NB 64
#define ND 4096
#define NV 50257
#define NCH 8
#define CH  6284   // 8*6284 = 50272 >= NV

// ---------------- scratch (device globals; no allocs allowed) ----------------
__device__ float g_At[(size_t)ND * NB];     // A transposed: At[k][m]
__device__ float g_part0[(size_t)NB * NV];
__device__ float g_part1[(size_t)NB * NV];
__device__ float g_part2[(size_t)NB * NV];
__device__ float g_logits[(size_t)NB * NV];
__device__ float g_exp[(size_t)NB * NV];
__device__ float g_thresh[NB];
__device__ float g_pval[NB * NCH];
__device__ int   g_pidx[NB * NCH];

// ---------------- packed fp32x2 FMA (Blackwell FFMA2) ----------------
__device__ __forceinline__ unsigned long long ffma2(unsigned long long a,
                                                    unsigned long long b,
                                                    unsigned long long c) {
    unsigned long long d;
    asm("fma.rn.f32x2 %0, %1, %2, %3;" : "=l"(d) : "l"(a), "l"(b), "l"(c));
    return d;
}

// ---------------- cp.async helpers ----------------
__device__ __forceinline__ void cp16(float* dst, const float* src) {
    unsigned d = (unsigned)__cvta_generic_to_shared(dst);
    asm volatile("cp.async.cg.shared.global [%0], [%1], 16;" :: "r"(d), "l"(src));
}
__device__ __forceinline__ void cp16_pred(float* dst, const float* src, bool ok) {
    unsigned d = (unsigned)__cvta_generic_to_shared(dst);
    int sz = ok ? 16 : 0;   // src-size 0 => zero-fill, no global read
    asm volatile("cp.async.cg.shared.global [%0], [%1], 16, %2;"
                 :: "r"(d), "l"(src), "r"(sz));
}
#define CP_COMMIT() asm volatile("cp.async.commit_group;")
#define CP_WAIT0()  asm volatile("cp.async.wait_group 0;")

// ---------------- A pre-transpose: At[k][m] = H[m][k] (1 MB, once) ----------------
__global__ void __launch_bounds__(256)
transpose_kernel(const float* __restrict__ H) {
    int g = blockIdx.x * 256 + threadIdx.x;   // 0 .. 64*4096-1
    int m = g >> 12, k = g & 4095;
    g_At[(size_t)k * NB + m] = H[g];
}

// ---------------- GEMM partials, split-K3, cp.async double-buffered ----------------
#define BKK  32
#define BPAD 36
#define GEMM_SMEM ((2*BKK*64 + 2*128*BPAD) * 4)   // 53248 B

__global__ void __launch_bounds__(128, 4)
gemm_kernel(const float* __restrict__ W) {
    extern __shared__ float sm[];
    float* Asm = sm;                   // [2][BKK][64]
    float* Bsm = sm + 2 * BKK * 64;    // [2][128][BPAD]

    const int tid = threadIdx.x;
    const int n0  = blockIdx.x * 128;
    const int s   = blockIdx.y;
    const int tmg = tid >> 4;    // 0..7
    const int tng = tid & 15;    // 0..15

    const int tile0  = (s == 0) ? 0 : (s == 1 ? 43 : 86);
    const int ntiles = (s == 2) ? 42 : 43;
    const int kbeg   = tile0 * BKK;

    const int  gn   = n0 + tid;
    const bool bok  = gn < NV;
    const float* bsrc_base = W + (size_t)(bok ? gn : 0) * ND;

    unsigned long long acc[4][8];
#pragma unroll
    for (int i = 0; i < 4; i++)
#pragma unroll
        for (int j = 0; j < 8; j++) acc[i][j] = 0ull;

    {
        const float* asrc = g_At + (size_t)kbeg * 64;
#pragma unroll
        for (int c = 0; c < 4; c++) {
            int chunk = tid + c * 128;
            cp16(Asm + chunk * 4, asrc + chunk * 4);
        }
        float* brow = Bsm + tid * BPAD;
        const float* bsrc = bsrc_base + kbeg;
#pragma unroll
        for (int c = 0; c < 8; c++) cp16_pred(brow + c * 4, bsrc + c * 4, bok);
        CP_COMMIT();
    }

    int buf = 0;
    for (int t = 0; t < ntiles; t++) {
        CP_WAIT0();
        __syncthreads();

        if (t + 1 < ntiles) {
            int k0n = kbeg + (t + 1) * BKK;
            int nb  = buf ^ 1;
            const float* asrc = g_At + (size_t)k0n * 64;
#pragma unroll
            for (int c = 0; c < 4; c++) {
                int chunk = tid + c * 128;
                cp16(Asm + nb * BKK * 64 + chunk * 4, asrc + chunk * 4);
            }
            float* brow = Bsm + nb * 128 * BPAD + tid * BPAD;
            const float* bsrc = bsrc_base + k0n;
#pragma unroll
            for (int c = 0; c < 8; c++) cp16_pred(brow + c * 4, bsrc + c * 4, bok);
            CP_COMMIT();
        }

        const float* Ab = Asm + buf * BKK * 64;
        const float* Bb = Bsm + buf * 128 * BPAD;
#pragma unroll 4
        for (int k = 0; k < BKK; k++) {
            float4 a01 = *(const float4*)(Ab + k * 64 + tmg * 8);
            float4 a23 = *(const float4*)(Ab + k * 64 + tmg * 8 + 4);
            unsigned long long ap[4];
            ap[0] = ((const unsigned long long*)&a01)[0];
            ap[1] = ((const unsigned long long*)&a01)[1];
            ap[2] = ((const unsigned long long*)&a23)[0];
            ap[3] = ((const unsigned long long*)&a23)[1];
            unsigned long long bp[8];
#pragma unroll
            for (int j = 0; j < 8; j++) {
                float w = Bb[(tng + 16 * j) * BPAD + k];
                unsigned wu = __float_as_uint(w);
                asm("mov.b64 %0, {%1, %1};" : "=l"(bp[j]) : "r"(wu));
            }
#pragma unroll
            for (int i = 0; i < 4; i++)
#pragma unroll
                for (int j = 0; j < 8; j++)
                    acc[i][j] = ffma2(ap[i], bp[j], acc[i][j]);
        }
        buf ^= 1;
    }

    float* outp = (s == 0) ? g_part0 : (s == 1 ? g_part1 : g_part2);
#pragma unroll
    for (int i = 0; i < 4; i++) {
        int m0 = tmg * 8 + 2 * i;
#pragma unroll
        for (int j = 0; j < 8; j++) {
            int n = n0 + tng + 16 * j;
            if (n < NV) {
                float2 v = *(float2*)&acc[i][j];
                outp[(size_t)m0 * NV + n]       = v.x;
                outp[(size_t)(m0 + 1) * NV + n] = v.y;
            }
        }
    }
}

// ---------------- block reductions (deterministic) ----------------
__device__ __forceinline__ float warpRedMax(float v) {
#pragma unroll
    for (int o = 16; o > 0; o >>= 1) v = fmaxf(v, __shfl_xor_sync(0xffffffffu, v, o));
    return v;
}
__device__ __forceinline__ float warpRedSum(float v) {
#pragma unroll
    for (int o = 16; o > 0; o >>= 1) v += __shfl_xor_sync(0xffffffffu, v, o);
    return v;
}
__device__ __forceinline__ float blockRedMax(float v, float* sred, float* bcast) {
    int tid = threadIdx.x, wid = tid >> 5, lid = tid & 31;
    __syncthreads();
    v = warpRedMax(v);
    if (lid == 0) sred[wid] = v;
    __syncthreads();
    if (wid == 0) {
        float x = sred[lid];
        x = warpRedMax(x);
        if (lid == 0) *bcast = x;
    }
    __syncthreads();
    return *bcast;
}
__device__ __forceinline__ float blockRedSum(float v, float* sred, float* bcast) {
    int tid = threadIdx.x, wid = tid >> 5, lid = tid & 31;
    __syncthreads();
    v = warpRedSum(v);
    if (lid == 0) sred[wid] = v;
    __syncthreads();
    if (wid == 0) {
        float x = sred[lid];
        x = warpRedSum(x);
        if (lid == 0) *bcast = x;
    }
    __syncthreads();
    return *bcast;
}

// ---------------- stats: combine partials, /T, softmax, octary top-p bisect ----
// Per sweep: 7 threshold sums + in-interval count reduced in ONE fused block
// reduction. Early-exit when no e remains in (lo, hi] (kept set frozen).
__global__ void __launch_bounds__(1024)
stats_kernel(const float* __restrict__ T, const float* __restrict__ top_p) {
    const int b = blockIdx.x, tid = threadIdx.x;
    const int wid = tid >> 5, lid = tid & 31;
    const float* P0 = g_part0 + (size_t)b * NV;
    const float* P1 = g_part1 + (size_t)b * NV;
    const float* P2 = g_part2 + (size_t)b * NV;
    float* L = g_logits + (size_t)b * NV;
    float* E = g_exp + (size_t)b * NV;
    __shared__ float sred[32];
    __shared__ float bcast;
    __shared__ float s8[32][8];
    __shared__ float b8[8];

    const float tb = T[b];
    float m = -3.4e38f;
    for (int v = tid; v < NV; v += 1024) {
        float l = (P0[v] + P1[v]) + P2[v];
        l = __fdiv_rn(l, tb);
        L[v] = l;
        m = fmaxf(m, l);
    }
    const float M = blockRedMax(m, sred, &bcast);

    float z = 0.f;
    for (int v = tid; v < NV; v += 1024) {
        float e = expf(L[v] - M);
        E[v] = e;
        z += e;
    }
    const float Z = blockRedSum(z, sred, &bcast);
    const float PZ = top_p[b] * Z;

    float lo = 0.f, hi = 1.0f;
    for (int it = 0; it < 16; it++) {
        float w = hi - lo;
        float t[7];
#pragma unroll
        for (int j = 0; j < 7; j++) t[j] = lo + w * ((float)(j + 1) * 0.125f);
        float acc8[8] = {0.f, 0.f, 0.f, 0.f, 0.f, 0.f, 0.f, 0.f};
        for (int v = tid; v < NV; v += 1024) {
            float e = E[v];
#pragma unroll
            for (int j = 0; j < 7; j++)
                if (e > t[j]) acc8[j] += e;
            if (e > lo && e <= hi) acc8[7] += 1.0f;
        }
        // fused block reduction of 8 values
        __syncthreads();
#pragma unroll
        for (int j = 0; j < 8; j++) acc8[j] = warpRedSum(acc8[j]);
        if (lid == 0)
#pragma unroll
            for (int j = 0; j < 8; j++) s8[wid][j] = acc8[j];
        __syncthreads();
        if (wid == 0) {
            float r8[8];
#pragma unroll
            for (int j = 0; j < 8; j++) r8[j] = s8[lid][j];
#pragma unroll
            for (int j = 0; j < 8; j++) r8[j] = warpRedSum(r8[j]);
            if (lid == 0)
#pragma unroll
                for (int j = 0; j < 8; j++) b8[j] = r8[j];
        }
        __syncthreads();
        float S[7];
#pragma unroll
        for (int j = 0; j < 7; j++) S[j] = b8[j];
        float inCnt = b8[7];

        int jstar = -1;
#pragma unroll
        for (int j = 0; j < 7; j++)
            if (S[j] > PZ) jstar = j;
        if (jstar < 0) {
            hi = t[0];
        } else {
            lo = t[jstar];
            if (jstar < 6) hi = t[jstar + 1];
        }
        if (inCnt == 0.f) break;   // no e inside interval: kept set frozen
        __syncthreads();
    }
    if (tid == 0) g_thresh[b] = lo;
}

// ---------------- JAX threefry2x32 (key = (0,42)) ----------------
__device__ __forceinline__ uint2 threefry(unsigned x0, unsigned x1) {
    const unsigned ks0 = 0u, ks1 = 42u;
    const unsigned ks2 = 0u ^ 42u ^ 0x1BD11BDAu;
    x0 += ks0; x1 += ks1;
#define TF_ROUND(r) { x0 += x1; x1 = (x1 << (r)) | (x1 >> (32 - (r))); x1 ^= x0; }
    TF_ROUND(13) TF_ROUND(15) TF_ROUND(26) TF_ROUND(6)
    x0 += ks1; x1 += ks2 + 1u;
    TF_ROUND(17) TF_ROUND(29) TF_ROUND(16) TF_ROUND(24)
    x0 += ks2; x1 += ks0 + 2u;
    TF_ROUND(13) TF_ROUND(15) TF_ROUND(26) TF_ROUND(6)
    x0 += ks0; x1 += ks1 + 3u;
    TF_ROUND(17) TF_ROUND(29) TF_ROUND(16) TF_ROUND(24)
    x0 += ks1; x1 += ks2 + 4u;
    TF_ROUND(13) TF_ROUND(15) TF_ROUND(26) TF_ROUND(6)
    x0 += ks2; x1 += ks0 + 5u;
#undef TF_ROUND
    return make_uint2(x0, x1);
}

// ---------------- sample: per-(row, vocab-chunk) partial argmax(l + gumbel) ----
// Partitionable threefry (JAX >= 0.4.30 default): counter (0, i), bits = out0 ^ out1.
#define STH 256
__global__ void __launch_bounds__(STH)
sample_kernel() {
    const int b = blockIdx.x, c = blockIdx.y, tid = threadIdx.x;
    const float* L = g_logits + (size_t)b * NV;
    const float* E = g_exp + (size_t)b * NV;
    const float thr = g_thresh[b];
    const int v0 = c * CH;
    const int v1 = min(v0 + CH, NV);
    __shared__ float rv[STH];
    __shared__ int   ri[STH];

    float best = -3.4e38f;
    int   bi = 0x7fffffff;
    for (int v = v0 + tid; v < v1; v += STH) {
        if (E[v] > thr) {
            float l = L[v];
            if (l + 17.0f >= best) {   // max gumbel ~= 16.64
                unsigned i = (unsigned)(b * NV + v);
                uint2 r = threefry(0u, i);
                unsigned bits = r.x ^ r.y;
                float u = __uint_as_float((bits >> 9) | 0x3f800000u) - 1.0f;
                if (u == 0.f) u = 1.17549435e-38f;
                float nl  = -logf(u);
                float gum = -logf(nl);
                float val = l + gum;
                if (val > best) { best = val; bi = v; }
            }
        }
    }
    rv[tid] = best; ri[tid] = bi; __syncthreads();
    for (int s = STH / 2; s > 0; s >>= 1) {
        if (tid < s) {
            if (rv[tid + s] > rv[tid] ||
                (rv[tid + s] == rv[tid] && ri[tid + s] < ri[tid])) {
                rv[tid] = rv[tid + s];
                ri[tid] = ri[tid + s];
            }
        }
        __syncthreads();
    }
    if (tid == 0) { g_pval[b * NCH + c] = rv[0]; g_pidx[b * NCH + c] = ri[0]; }
}

// ---------------- final: combine chunk partials (ascending => lowest-idx ties) ----
__global__ void __launch_bounds__(64)
final_kernel(float* __restrict__ out) {
    int b = threadIdx.x;
    float best = -3.4e38f;
    int   bi = 0x7fffffff;
#pragma unroll
    for (int c = 0; c < NCH; c++) {
        float v = g_pval[b * NCH + c];
        int   i = g_pidx[b * NCH + c];
        if (v > best || (v == best && i < bi)) { best = v; bi = i; }
    }
    out[b] = (float)bi;
}

// ---------------- launch ----------------
extern "C" void kernel_launch(void* const* d_in, const int* in_sizes, int n_in,
                              void* d_out, int out_size) {
    const float* H  = nullptr;
    const float* W  = nullptr;
    const float* T  = nullptr;
    const float* TP = nullptr;
    for (int i = 0; i < n_in; i++) {
        if (in_sizes[i] == NB * ND) {
            H = (const float*)d_in[i];
        } else if (in_sizes[i] == NV * ND) {
            W = (const float*)d_in[i];
        } else if (in_sizes[i] == NB) {
            if (!T) T = (const float*)d_in[i];
            else    TP = (const float*)d_in[i];
        }
    }
    if (!H || !W || !T || !TP) {   // fallback: signature order
        H  = (const float*)d_in[0];
        W  = (const float*)d_in[1];
        T  = (const float*)d_in[2];
        TP = (const float*)d_in[3];
    }
    float* out = (float*)d_out;

    cudaFuncSetAttribute(gemm_kernel,
                         cudaFuncAttributeMaxDynamicSharedMemorySize, GEMM_SMEM);

    transpose_kernel<<<(NB * ND) / 256, 256>>>(H);
    dim3 gg((NV + 127) / 128, 3);
    gemm_kernel<<<gg, 128, GEMM_SMEM>>>(W);
    stats_kernel<<<NB, 1024>>>(T, TP);
    dim3 sg(NB, NCH);
    sample_kernel<<<sg, STH>>>();
    final_kernel<<<1, 64>>>(out);
}